// round 5
// baseline (speedup 1.0000x reference)
#include <cuda_runtime.h>

// nlwt_catone: fused non-linear wavelet transform
// x: [8, 32, 512, 512] f32  ->  out: [8, 128, 256, 256] f32
//
// out[b, s*32+c, i, j] = sum_k M2[s][k] * a_k where
//   a0 = M1[0] . patch(i, j)
//   a1 = M1[1] . patch((i+1)%H1, j)
//   a2 = M1[2] . patch(i, (j+1)%W1)
//   a3 = M1[3] . patch((i+1)%H1, (j+1)%W1)
//
// R5: R3 base (best: 1 row/block-row, 2 cols/thread, __stcs stores) with the
// 4 redundant column-wrap LDG.64s replaced by warp shuffles (thread t's wrap
// data == thread t+1's float4.xy). Lane 31 still does the real (warp-edge /
// roll) loads.

#define Hd   512
#define Wd   512
#define H1d  256
#define W1d  256
#define Cd   32
#define FULL 0xFFFFFFFFu

__device__ __forceinline__ float dot4(float m0, float m1, float m2, float m3,
                                      float p0, float p1, float p2, float p3) {
    return fmaf(m0, p0, fmaf(m1, p1, fmaf(m2, p2, m3 * p3)));
}

__global__ __launch_bounds__(128, 8)
void nlwt_kernel(const float* __restrict__ x, float* __restrict__ out) {
    const int tx   = threadIdx.x;      // 0..127
    const int lane = tx & 31;
    const int i    = blockIdx.x;       // output row 0..255
    const int bc   = blockIdx.y;       // b*32 + c
    const int j0   = tx * 2;           // output col (even)
    const int c0   = j0 * 2;           // input col = 4*tx (16B aligned)

    const int i1 = (i + 1 == H1d) ? 0 : i + 1;          // row roll
    const int cn = (j0 + 2 == W1d) ? 0 : c0 + 4;        // col roll (lane-31 load)

    const float* base = x + (size_t)bc * (Hd * Wd);
    const float* r0a = base + (size_t)(2 * i)  * Wd;    // row 2i
    const float* r0b = r0a + Wd;                         // row 2i+1
    const float* r1a = base + (size_t)(2 * i1) * Wd;    // row 2*i1
    const float* r1b = r1a + Wd;                         // row 2*i1+1

    // Main 4x4 neighborhood (4 x LDG.128)
    const float4 A  = *(const float4*)(r0a + c0);
    const float4 B  = *(const float4*)(r0b + c0);
    const float4 Cv = *(const float4*)(r1a + c0);
    const float4 D  = *(const float4*)(r1b + c0);

    // Column-wrap values via shuffle: thread t needs thread (t+1)'s (.x, .y).
    float2 A2, B2, C2, D2;
    A2.x = __shfl_down_sync(FULL, A.x,  1);  A2.y = __shfl_down_sync(FULL, A.y,  1);
    B2.x = __shfl_down_sync(FULL, B.x,  1);  B2.y = __shfl_down_sync(FULL, B.y,  1);
    C2.x = __shfl_down_sync(FULL, Cv.x, 1);  C2.y = __shfl_down_sync(FULL, Cv.y, 1);
    D2.x = __shfl_down_sync(FULL, D.x,  1);  D2.y = __shfl_down_sync(FULL, D.y,  1);
    if (lane == 31) {                        // warp edge (incl. roll wrap)
        A2 = *(const float2*)(r0a + cn);
        B2 = *(const float2*)(r0b + cn);
        C2 = *(const float2*)(r1a + cn);
        D2 = *(const float2*)(r1b + cn);
    }

    // M1 rows:
    //  0.8664  0.1026  0.4852 -0.0574
    // -0.1026  0.8664 -0.0574 -0.4852
    //  0.4852  0.0574 -0.8664  0.1026
    //  0.0574 -0.4852 -0.1026 -0.8664

    // position (i, j0)
    const float a0_0 = dot4( 0.8664f,  0.1026f,  0.4852f, -0.0574f, A.x,  A.y,  B.x,  B.y);
    const float a1_0 = dot4(-0.1026f,  0.8664f, -0.0574f, -0.4852f, Cv.x, Cv.y, D.x,  D.y);
    const float a2_0 = dot4( 0.4852f,  0.0574f, -0.8664f,  0.1026f, A.z,  A.w,  B.z,  B.w);
    const float a3_0 = dot4( 0.0574f, -0.4852f, -0.1026f, -0.8664f, Cv.z, Cv.w, D.z,  D.w);

    // position (i, j0+1)
    const float a0_1 = dot4( 0.8664f,  0.1026f,  0.4852f, -0.0574f, A.z,  A.w,  B.z,  B.w);
    const float a1_1 = dot4(-0.1026f,  0.8664f, -0.0574f, -0.4852f, Cv.z, Cv.w, D.z,  D.w);
    const float a2_1 = dot4( 0.4852f,  0.0574f, -0.8664f,  0.1026f, A2.x, A2.y, B2.x, B2.y);
    const float a3_1 = dot4( 0.0574f, -0.4852f, -0.1026f, -0.8664f, C2.x, C2.y, D2.x, D2.y);

    // M2 rows:
    //  1.3968  0.2212 -0.2212 -1.3968
    // -0.2212  1.3968 -1.3968  0.2212
    // -0.5412 -1.3066 -1.3066 -0.5412
    //  1.3066 -0.5412 -0.5412  1.3066
    float2 o0, o1, o2, o3;
    o0.x = dot4( 1.3968f,  0.2212f, -0.2212f, -1.3968f, a0_0, a1_0, a2_0, a3_0);
    o1.x = dot4(-0.2212f,  1.3968f, -1.3968f,  0.2212f, a0_0, a1_0, a2_0, a3_0);
    o2.x = dot4(-0.5412f, -1.3066f, -1.3066f, -0.5412f, a0_0, a1_0, a2_0, a3_0);
    o3.x = dot4( 1.3066f, -0.5412f, -0.5412f,  1.3066f, a0_0, a1_0, a2_0, a3_0);
    o0.y = dot4( 1.3968f,  0.2212f, -0.2212f, -1.3968f, a0_1, a1_1, a2_1, a3_1);
    o1.y = dot4(-0.2212f,  1.3968f, -1.3968f,  0.2212f, a0_1, a1_1, a2_1, a3_1);
    o2.y = dot4(-0.5412f, -1.3066f, -1.3066f, -0.5412f, a0_1, a1_1, a2_1, a3_1);
    o3.y = dot4( 1.3066f, -0.5412f, -0.5412f,  1.3066f, a0_1, a1_1, a2_1, a3_1);

    // out[b, s*32 + c, i, j] ; bc = b*32 + c
    const int b = bc >> 5;
    const int c = bc & 31;
    const size_t sband = (size_t)Cd * H1d * W1d;        // stride per subband
    float* op = out + ((size_t)(b * 4 * Cd + c) * H1d + i) * W1d + j0;

    __stcs((float2*)(op),             o0);
    __stcs((float2*)(op + sband),     o1);
    __stcs((float2*)(op + 2 * sband), o2);
    __stcs((float2*)(op + 3 * sband), o3);
}

extern "C" void kernel_launch(void* const* d_in, const int* in_sizes, int n_in,
                              void* d_out, int out_size) {
    const float* x = (const float*)d_in[0];
    float* out = (float*)d_out;
    dim3 grid(H1d, 8 * Cd);   // (256 rows, 256 bc slices)
    nlwt_kernel<<<grid, 128>>>(x, out);
}

// round 6
// speedup vs baseline: 1.0023x; 1.0023x over previous
#include <cuda_runtime.h>

// nlwt_catone: fused non-linear wavelet transform
// x: [8, 32, 512, 512] f32  ->  out: [8, 128, 256, 256] f32
//
// out[b, s*32+c, i, j] = sum_k M2[s][k] * a_k where
//   a0 = M1[0] . patch(i, j)
//   a1 = M1[1] . patch((i+1)%H1, j)
//   a2 = M1[2] . patch(i, (j+1)%W1)
//   a3 = M1[3] . patch((i+1)%H1, (j+1)%W1)
// patch(p,q) = [x(2p,2q), x(2p,2q+1), x(2p+1,2q), x(2p+1,2q+1)] within (b,c).
//
// R6: per-thread body identical to R3 (best: 2 cols/thread, 128-thread blocks,
// __stcs streaming stores, 32 regs, occ ~88%). Only change: grid dims swapped
// (blockIdx.x = bc, blockIdx.y = row) so each scheduling wave spreads its
// reads across all 256 images -> uniform DRAM channel pressure. Roll-row
// reuse becomes wave-to-wave (working set ~1 MB, trivially L2-resident).

#define Hd   512
#define Wd   512
#define H1d  256
#define W1d  256
#define Cd   32

__device__ __forceinline__ float dot4(float m0, float m1, float m2, float m3,
                                      float p0, float p1, float p2, float p3) {
    return fmaf(m0, p0, fmaf(m1, p1, fmaf(m2, p2, m3 * p3)));
}

__global__ __launch_bounds__(128, 8)
void nlwt_kernel(const float* __restrict__ x, float* __restrict__ out) {
    const int tx = threadIdx.x;        // 0..127
    const int bc = blockIdx.x;         // b*32 + c, 0..255  (fast grid dim)
    const int i  = blockIdx.y;         // output row 0..255
    const int j0 = tx * 2;             // output col (even)
    const int c0 = j0 * 2;             // input col = 4*tx (16B aligned)

    const int i1 = (i + 1 == H1d) ? 0 : i + 1;          // row roll
    const int cn = (j0 + 2 == W1d) ? 0 : c0 + 4;        // col roll

    const float* base = x + (size_t)bc * (Hd * Wd);
    const float* r0a = base + (size_t)(2 * i)  * Wd;    // row 2i
    const float* r0b = r0a + Wd;                         // row 2i+1
    const float* r1a = base + (size_t)(2 * i1) * Wd;    // row 2*i1
    const float* r1b = r1a + Wd;                         // row 2*i1+1

    // 4x4 (+wrap) input neighborhood, vectorized
    const float4 A  = *(const float4*)(r0a + c0);
    const float4 B  = *(const float4*)(r0b + c0);
    const float4 Cv = *(const float4*)(r1a + c0);
    const float4 D  = *(const float4*)(r1b + c0);
    const float2 A2 = *(const float2*)(r0a + cn);
    const float2 B2 = *(const float2*)(r0b + cn);
    const float2 C2 = *(const float2*)(r1a + cn);
    const float2 D2 = *(const float2*)(r1b + cn);

    // M1 rows:
    //  0.8664  0.1026  0.4852 -0.0574
    // -0.1026  0.8664 -0.0574 -0.4852
    //  0.4852  0.0574 -0.8664  0.1026
    //  0.0574 -0.4852 -0.1026 -0.8664

    // position (i, j0)
    const float a0_0 = dot4( 0.8664f,  0.1026f,  0.4852f, -0.0574f, A.x,  A.y,  B.x,  B.y);
    const float a1_0 = dot4(-0.1026f,  0.8664f, -0.0574f, -0.4852f, Cv.x, Cv.y, D.x,  D.y);
    const float a2_0 = dot4( 0.4852f,  0.0574f, -0.8664f,  0.1026f, A.z,  A.w,  B.z,  B.w);
    const float a3_0 = dot4( 0.0574f, -0.4852f, -0.1026f, -0.8664f, Cv.z, Cv.w, D.z,  D.w);

    // position (i, j0+1)
    const float a0_1 = dot4( 0.8664f,  0.1026f,  0.4852f, -0.0574f, A.z,  A.w,  B.z,  B.w);
    const float a1_1 = dot4(-0.1026f,  0.8664f, -0.0574f, -0.4852f, Cv.z, Cv.w, D.z,  D.w);
    const float a2_1 = dot4( 0.4852f,  0.0574f, -0.8664f,  0.1026f, A2.x, A2.y, B2.x, B2.y);
    const float a3_1 = dot4( 0.0574f, -0.4852f, -0.1026f, -0.8664f, C2.x, C2.y, D2.x, D2.y);

    // M2 rows:
    //  1.3968  0.2212 -0.2212 -1.3968
    // -0.2212  1.3968 -1.3968  0.2212
    // -0.5412 -1.3066 -1.3066 -0.5412
    //  1.3066 -0.5412 -0.5412  1.3066
    float2 o0, o1, o2, o3;
    o0.x = dot4( 1.3968f,  0.2212f, -0.2212f, -1.3968f, a0_0, a1_0, a2_0, a3_0);
    o1.x = dot4(-0.2212f,  1.3968f, -1.3968f,  0.2212f, a0_0, a1_0, a2_0, a3_0);
    o2.x = dot4(-0.5412f, -1.3066f, -1.3066f, -0.5412f, a0_0, a1_0, a2_0, a3_0);
    o3.x = dot4( 1.3066f, -0.5412f, -0.5412f,  1.3066f, a0_0, a1_0, a2_0, a3_0);
    o0.y = dot4( 1.3968f,  0.2212f, -0.2212f, -1.3968f, a0_1, a1_1, a2_1, a3_1);
    o1.y = dot4(-0.2212f,  1.3968f, -1.3968f,  0.2212f, a0_1, a1_1, a2_1, a3_1);
    o2.y = dot4(-0.5412f, -1.3066f, -1.3066f, -0.5412f, a0_1, a1_1, a2_1, a3_1);
    o3.y = dot4( 1.3066f, -0.5412f, -0.5412f,  1.3066f, a0_1, a1_1, a2_1, a3_1);

    // out[b, s*32 + c, i, j] ; bc = b*32 + c
    const int b = bc >> 5;
    const int c = bc & 31;
    const size_t sband = (size_t)Cd * H1d * W1d;        // stride per subband
    float* op = out + ((size_t)(b * 4 * Cd + c) * H1d + i) * W1d + j0;

    __stcs((float2*)(op),             o0);
    __stcs((float2*)(op + sband),     o1);
    __stcs((float2*)(op + 2 * sband), o2);
    __stcs((float2*)(op + 3 * sband), o3);
}

extern "C" void kernel_launch(void* const* d_in, const int* in_sizes, int n_in,
                              void* d_out, int out_size) {
    const float* x = (const float*)d_in[0];
    float* out = (float*)d_out;
    dim3 grid(8 * Cd, H1d);   // (256 bc slices fast, 256 rows slow)
    nlwt_kernel<<<grid, 128>>>(x, out);
}

// round 7
// speedup vs baseline: 1.0300x; 1.0276x over previous
#include <cuda_runtime.h>

// nlwt_catone: fused non-linear wavelet transform  — FINAL (R3 config)
// x: [8, 32, 512, 512] f32  ->  out: [8, 128, 256, 256] f32
//
// out[b, s*32+c, i, j] = sum_k M2[s][k] * a_k where
//   a0 = M1[0] . patch(i, j)
//   a1 = M1[1] . patch((i+1)%H1, j)
//   a2 = M1[2] . patch(i, (j+1)%W1)
//   a3 = M1[3] . patch((i+1)%H1, (j+1)%W1)
// patch(p,q) = [x(2p,2q), x(2p,2q+1), x(2p+1,2q), x(2p+1,2q+1)] within (b,c).
//
// Config (best of 6 rounds, HBM-floor-bound at ~6.4 TB/s / 80% DRAM busy):
//   - 1 output row per blockIdx.x, bc per blockIdx.y (row-major wave order:
//     block i's roll rows == block i+1's main rows -> L2-adjacent fetches)
//   - 2 output cols/thread, 128-thread blocks, 32 regs, occ ~88%
//   - fully vectorized: 4x LDG.128 + 4x LDG.64 in, 4x STG.64 streaming out
//   - roll wrap via power-of-two masks

#define Hd   512
#define Wd   512
#define H1d  256
#define W1d  256
#define Cd   32

__device__ __forceinline__ float dot4(float m0, float m1, float m2, float m3,
                                      float p0, float p1, float p2, float p3) {
    return fmaf(m0, p0, fmaf(m1, p1, fmaf(m2, p2, m3 * p3)));
}

__global__ __launch_bounds__(128, 8)
void nlwt_kernel(const float* __restrict__ x, float* __restrict__ out) {
    const int tx = threadIdx.x;        // 0..127
    const int i  = blockIdx.x;         // output row 0..255
    const int bc = blockIdx.y;         // b*32 + c, 0..255
    const int j0 = tx * 2;             // output col (even)
    const int c0 = j0 * 2;             // input col = 4*tx (16B aligned)

    const int i1 = (i + 1) & (H1d - 1);          // row roll
    const int cn = (c0 + 4) & (Wd - 1);          // col roll (input index)

    const float* base = x + (size_t)bc * (Hd * Wd);
    const float* r0a = base + (size_t)(2 * i)  * Wd;    // row 2i
    const float* r0b = r0a + Wd;                         // row 2i+1
    const float* r1a = base + (size_t)(2 * i1) * Wd;    // row 2*i1
    const float* r1b = r1a + Wd;                         // row 2*i1+1

    // 4x4 (+wrap) input neighborhood, vectorized
    const float4 A  = *(const float4*)(r0a + c0);
    const float4 B  = *(const float4*)(r0b + c0);
    const float4 Cv = *(const float4*)(r1a + c0);
    const float4 D  = *(const float4*)(r1b + c0);
    const float2 A2 = *(const float2*)(r0a + cn);
    const float2 B2 = *(const float2*)(r0b + cn);
    const float2 C2 = *(const float2*)(r1a + cn);
    const float2 D2 = *(const float2*)(r1b + cn);

    // M1 rows:
    //  0.8664  0.1026  0.4852 -0.0574
    // -0.1026  0.8664 -0.0574 -0.4852
    //  0.4852  0.0574 -0.8664  0.1026
    //  0.0574 -0.4852 -0.1026 -0.8664

    // position (i, j0)
    const float a0_0 = dot4( 0.8664f,  0.1026f,  0.4852f, -0.0574f, A.x,  A.y,  B.x,  B.y);
    const float a1_0 = dot4(-0.1026f,  0.8664f, -0.0574f, -0.4852f, Cv.x, Cv.y, D.x,  D.y);
    const float a2_0 = dot4( 0.4852f,  0.0574f, -0.8664f,  0.1026f, A.z,  A.w,  B.z,  B.w);
    const float a3_0 = dot4( 0.0574f, -0.4852f, -0.1026f, -0.8664f, Cv.z, Cv.w, D.z,  D.w);

    // position (i, j0+1)
    const float a0_1 = dot4( 0.8664f,  0.1026f,  0.4852f, -0.0574f, A.z,  A.w,  B.z,  B.w);
    const float a1_1 = dot4(-0.1026f,  0.8664f, -0.0574f, -0.4852f, Cv.z, Cv.w, D.z,  D.w);
    const float a2_1 = dot4( 0.4852f,  0.0574f, -0.8664f,  0.1026f, A2.x, A2.y, B2.x, B2.y);
    const float a3_1 = dot4( 0.0574f, -0.4852f, -0.1026f, -0.8664f, C2.x, C2.y, D2.x, D2.y);

    // M2 rows:
    //  1.3968  0.2212 -0.2212 -1.3968
    // -0.2212  1.3968 -1.3968  0.2212
    // -0.5412 -1.3066 -1.3066 -0.5412
    //  1.3066 -0.5412 -0.5412  1.3066
    float2 o0, o1, o2, o3;
    o0.x = dot4( 1.3968f,  0.2212f, -0.2212f, -1.3968f, a0_0, a1_0, a2_0, a3_0);
    o1.x = dot4(-0.2212f,  1.3968f, -1.3968f,  0.2212f, a0_0, a1_0, a2_0, a3_0);
    o2.x = dot4(-0.5412f, -1.3066f, -1.3066f, -0.5412f, a0_0, a1_0, a2_0, a3_0);
    o3.x = dot4( 1.3066f, -0.5412f, -0.5412f,  1.3066f, a0_0, a1_0, a2_0, a3_0);
    o0.y = dot4( 1.3968f,  0.2212f, -0.2212f, -1.3968f, a0_1, a1_1, a2_1, a3_1);
    o1.y = dot4(-0.2212f,  1.3968f, -1.3968f,  0.2212f, a0_1, a1_1, a2_1, a3_1);
    o2.y = dot4(-0.5412f, -1.3066f, -1.3066f, -0.5412f, a0_1, a1_1, a2_1, a3_1);
    o3.y = dot4( 1.3066f, -0.5412f, -0.5412f,  1.3066f, a0_1, a1_1, a2_1, a3_1);

    // out[b, s*32 + c, i, j] ; bc = b*32 + c
    const int b = bc >> 5;
    const int c = bc & 31;
    const size_t sband = (size_t)Cd * H1d * W1d;        // stride per subband
    float* op = out + ((size_t)(b * 4 * Cd + c) * H1d + i) * W1d + j0;

    // Streaming stores: outputs have zero reuse.
    __stcs((float2*)(op),             o0);
    __stcs((float2*)(op + sband),     o1);
    __stcs((float2*)(op + 2 * sband), o2);
    __stcs((float2*)(op + 3 * sband), o3);
}

extern "C" void kernel_launch(void* const* d_in, const int* in_sizes, int n_in,
                              void* d_out, int out_size) {
    const float* x = (const float*)d_in[0];
    float* out = (float*)d_out;
    dim3 grid(H1d, 8 * Cd);   // (256 rows fast, 256 bc slices slow)
    nlwt_kernel<<<grid, 128>>>(x, out);
}